// round 11
// baseline (speedup 1.0000x reference)
#include <cuda_runtime.h>
#include <stdint.h>

#define QN     256
#define DIM    128
#define NLIST  1024
#define MSUB   8
#define KCODE  256
#define DSUB   16
#define NPROBE 32
#define TOPK   100
#define MAXN   250000
#define NBIN   4096
#define BUFSZ  4096

typedef unsigned long long u64;
typedef unsigned int       u32;

// monotonic float->uint transform (total order preserving)
__device__ __forceinline__ u32 f2s(float f) {
    u32 u = __float_as_uint(f);
    return u ^ ((u >> 31) ? 0xFFFFFFFFu : 0x80000000u);
}

// XLA-GPU style row-norm: lane t sums 4 CONTIGUOUS rounded products
// sequentially, then shfl-down butterfly tree (16,8,4,2,1). Valid in lane 0.
__device__ __forceinline__ float warp_norm128(const float* __restrict__ row, int lane)
{
    float p0 = __fmul_rn(row[4 * lane + 0], row[4 * lane + 0]);
    float p1 = __fmul_rn(row[4 * lane + 1], row[4 * lane + 1]);
    float p2 = __fmul_rn(row[4 * lane + 2], row[4 * lane + 2]);
    float p3 = __fmul_rn(row[4 * lane + 3], row[4 * lane + 3]);
    float s  = __fadd_rn(__fadd_rn(__fadd_rn(p0, p1), p2), p3);
    #pragma unroll
    for (int off = 16; off > 0; off >>= 1)
        s = __fadd_rn(s, __shfl_down_sync(0xFFFFFFFFu, s, off));
    return s;   // lane 0
}

// precomputed centroid norms (XLA-reduce order), one warp per row
__device__ float g_cnf[NLIST];

__global__ void __launch_bounds__(256) k_cnorm(const float* __restrict__ centroids)
{
    int wid  = blockIdx.x * 8 + (threadIdx.x >> 5);
    int lane = threadIdx.x & 31;
    if (wid < NLIST) {
        float s = warp_norm128(centroids + (size_t)wid * DIM, lane);
        if (lane == 0) g_cnf[wid] = s;
    }
}

// =============================================================================
// Fused kernel, one CTA (256 threads) per query. Static smem only (~44.6 KB).
// Numerics bit-match the presumed XLA scheme:
//   dots  : sequential f32 FMA chains, ascending index (GEMM thread order)
//   norms : rounded products + XLA row-reduce order (warp_norm128) for D=128,
//           plain sequential for D=16 (loop emitter)
//   combos: (qq + cc) - 2*dot ; ADC sum sequential in m
// =============================================================================
__global__ void __launch_bounds__(256) k_fused(const float* __restrict__ queries,
                                               const float* __restrict__ codebooks,
                                               const int*   __restrict__ db_codes,
                                               const int*   __restrict__ db_list,
                                               const float* __restrict__ centroids,
                                               int N,
                                               float* __restrict__ out)
{
    __shared__ __align__(16) unsigned char SM[32768];   // phase-aliased
    u64* ckey   = (u64*)SM;            // phase 1: 1024 coarse keys
    u32* hist4k = (u32*)SM;            // phase 3a: 4096-bin histogram
    u64* buf    = (u64*)SM;            // phase 3b: <=4096 collected keys

    __shared__ float lut[MSUB * KCODE];
    __shared__ float qsm[DIM];
    __shared__ unsigned char mask[NLIST];
    __shared__ u32   hist256[256];
    __shared__ u64   sel[128];
    __shared__ u64   wmin[8];
    __shared__ u64   s_g;
    __shared__ float s_qnf;
    __shared__ int   s_cnt, s_k, s_bstar, s_total;
    __shared__ u32   s_pfx;

    int t = threadIdx.x;
    int q = blockIdx.x;

    if (t < DIM) qsm[t] = queries[q * DIM + t];
    for (int i = t; i < NLIST; i += 256) mask[i] = 0;
    if (t == 0) { s_cnt = 0; s_bstar = -1; }
    __syncthreads();

    // ---------- phase 1: coarse distances (reference-order f32) -------------
    if (t < 32) {
        float s = warp_norm128(qsm, t);
        if (t == 0) s_qnf = s;
    }
    __syncthreads();
    float qnf = s_qnf;

    #pragma unroll
    for (int s = 0; s < 4; ++s) {
        int l = t + s * 256;
        const float* cr = centroids + (size_t)l * DIM;
        float dq = 0.f;                       // sequential FMA, k ascending
        #pragma unroll 8
        for (int d = 0; d < DIM; ++d)
            dq = __fmaf_rn(qsm[d], __ldg(cr + d), dq);
        float dist = __fsub_rn(__fadd_rn(qnf, g_cnf[l]), __fmul_rn(2.f, dq));
        ckey[l] = (((u64)f2s(dist)) << 32) | (u32)l;
    }
    __syncthreads();

    // exact top-32 via 32 rounds of block argmin (keys unique)
    for (int r = 0; r < NPROBE; ++r) {
        u64 lm = ~0ULL;
        #pragma unroll
        for (int s = 0; s < 4; ++s) { u64 k = ckey[t + s * 256]; if (k < lm) lm = k; }
        #pragma unroll
        for (int off = 16; off > 0; off >>= 1) {
            u64 o = __shfl_down_sync(0xFFFFFFFFu, lm, off);
            if (o < lm) lm = o;
        }
        if ((t & 31) == 0) wmin[t >> 5] = lm;
        __syncthreads();
        if (t == 0) {
            u64 g = wmin[0];
            #pragma unroll
            for (int w = 1; w < 8; ++w) if (wmin[w] < g) g = wmin[w];
            s_g = g;
            mask[(int)(g & (NLIST - 1))] = 1;
        }
        __syncthreads();
        u64 g = s_g;
        #pragma unroll
        for (int s = 0; s < 4; ++s)
            if (ckey[t + s * 256] == g) ckey[t + s * 256] = ~0ULL;
        __syncthreads();
    }

    // ---------- phase 2: ADC LUT (reference-order f32) ----------------------
    #pragma unroll
    for (int m = 0; m < MSUB; ++m) {
        const float* cb = codebooks + ((size_t)(m * KCODE + t)) * DSUB;
        const float* qm = qsm + m * DSUB;
        float cn = 0.f, qns = 0.f, dq = 0.f;
        #pragma unroll
        for (int d = 0; d < DSUB; ++d) {
            float c = __ldg(cb + d);
            cn  = __fadd_rn(cn,  __fmul_rn(c, c));          // seq, rounded prods
            qns = __fadd_rn(qns, __fmul_rn(qm[d], qm[d]));  // seq, rounded prods
            dq  = __fmaf_rn(qm[d], c, dq);                  // seq FMA (gemm)
        }
        lut[m * KCODE + t] = __fsub_rn(__fadd_rn(qns, cn), __fmul_rn(2.f, dq));
    }
    __syncthreads();   // ckey dead; SM becomes hist4k

    // ---------- phase 3a: histogram of 12-bit distance-key prefixes ----------
    for (int i = t; i < NBIN; i += 256) hist4k[i] = 0;
    __syncthreads();

    for (int n = t; n < N; n += 256) {
        int l = db_list[n];
        if ((u32)l < (u32)NLIST && mask[l]) {
            const int4* cp = (const int4*)(db_codes + (size_t)n * MSUB);
            int4 c0 = __ldg(cp);
            int4 c1 = __ldg(cp + 1);
            float dsum = lut[c0.x & 255];          // sequential f32, m = 0..7
            dsum = __fadd_rn(dsum, lut[KCODE     + (c0.y & 255)]);
            dsum = __fadd_rn(dsum, lut[2 * KCODE + (c0.z & 255)]);
            dsum = __fadd_rn(dsum, lut[3 * KCODE + (c0.w & 255)]);
            dsum = __fadd_rn(dsum, lut[4 * KCODE + (c1.x & 255)]);
            dsum = __fadd_rn(dsum, lut[5 * KCODE + (c1.y & 255)]);
            dsum = __fadd_rn(dsum, lut[6 * KCODE + (c1.z & 255)]);
            dsum = __fadd_rn(dsum, lut[7 * KCODE + (c1.w & 255)]);
            atomicAdd(&hist4k[f2s(dsum) >> 20], 1u);
        }
    }
    __syncthreads();

    {
        u32 gsum = 0;
        #pragma unroll
        for (int i = 0; i < 16; ++i) gsum += hist4k[t * 16 + i];
        hist256[t] = gsum;
        __syncthreads();
        for (int off = 1; off < 256; off <<= 1) {
            u32 v = (t >= off) ? hist256[t - off] : 0u;
            __syncthreads();
            hist256[t] += v;
            __syncthreads();
        }
        int total = (int)hist256[255];
        if (t == 0) s_total = total;
        int ksel = (total < TOPK) ? total : TOPK;
        u32 cumEnd   = hist256[t];
        u32 cumStart = cumEnd - gsum;
        if (total > 0 && (int)cumStart < ksel && (int)cumEnd >= ksel) {
            int c = (int)cumStart;
            #pragma unroll
            for (int i = 0; i < 16; ++i) {
                c += (int)hist4k[t * 16 + i];
                if (c >= ksel) { s_bstar = t * 16 + i; break; }
            }
        }
    }
    __syncthreads();

    int total = s_total;
    int bstar = s_bstar;
    if (total == 0 || bstar < 0) {
        if (t < TOPK) out[q * TOPK + t] = 0.f;   // unreachable for this data
        return;
    }
    __syncthreads();   // hist4k dead; SM becomes buf

    // ---------- phase 3b: collect keys with prefix <= bstar ------------------
    if (t == 0) s_cnt = 0;
    __syncthreads();
    for (int n = t; n < N; n += 256) {
        int l = db_list[n];
        if ((u32)l < (u32)NLIST && mask[l]) {
            const int4* cp = (const int4*)(db_codes + (size_t)n * MSUB);
            int4 c0 = __ldg(cp);
            int4 c1 = __ldg(cp + 1);
            float dsum = lut[c0.x & 255];
            dsum = __fadd_rn(dsum, lut[KCODE     + (c0.y & 255)]);
            dsum = __fadd_rn(dsum, lut[2 * KCODE + (c0.z & 255)]);
            dsum = __fadd_rn(dsum, lut[3 * KCODE + (c0.w & 255)]);
            dsum = __fadd_rn(dsum, lut[4 * KCODE + (c1.x & 255)]);
            dsum = __fadd_rn(dsum, lut[5 * KCODE + (c1.y & 255)]);
            dsum = __fadd_rn(dsum, lut[6 * KCODE + (c1.z & 255)]);
            dsum = __fadd_rn(dsum, lut[7 * KCODE + (c1.w & 255)]);
            u32 dk = f2s(dsum);
            if ((int)(dk >> 20) <= bstar) {
                int pos = atomicAdd(&s_cnt, 1);
                if (pos < BUFSZ)
                    buf[pos] = (((u64)dk) << 32) | (u32)n;
            }
        }
    }
    __syncthreads();

    int C = s_cnt;
    if (C > BUFSZ) C = BUFSZ;
    int ksel = (total < TOPK) ? total : TOPK;
    if (ksel > C) ksel = C;

    // ---------- phase 4a: exact radix select of ksel-th smallest dist key ----
    if (t == 0) { s_pfx = 0u; s_k = ksel; }
    int iters = (C + 255) >> 8;
    for (int pass = 3; pass >= 0; --pass) {
        __syncthreads();
        u32 prefix = s_pfx;
        int kk     = s_k;
        int shift  = pass * 8;
        u32 pmask  = (pass == 3) ? 0u : (0xFFFFFFFFu << (shift + 8));
        hist256[t] = 0;
        __syncthreads();
        for (int it = 0; it < iters; ++it) {
            int j = (it << 8) + t;
            if (j < C) {
                u32 dk = (u32)(buf[j] >> 32);
                if ((dk & pmask) == prefix)
                    atomicAdd(&hist256[(dk >> shift) & 0xFF], 1u);
            }
        }
        __syncthreads();
        for (int off = 1; off < 256; off <<= 1) {
            u32 v = (t >= off) ? hist256[t - off] : 0u;
            __syncthreads();
            hist256[t] += v;
            __syncthreads();
        }
        u32 cum  = hist256[t];
        u32 prev = (t == 0) ? 0u : hist256[t - 1];
        if ((int)cum >= kk && (int)prev < kk) {
            s_pfx = prefix | ((u32)t << shift);
            s_k   = kk - (int)prev;
        }
    }
    __syncthreads();
    u32 kth = s_pfx;

    // ---------- phase 4b: compact (<= kth), bitonic sort 128, emit -----------
    if (t == 0) s_cnt = 0;
    if (t < 128) sel[t] = ~0ULL;
    __syncthreads();
    for (int j = t; j < C; j += 256) {
        u64 key = buf[j];
        if ((u32)(key >> 32) <= kth) {
            int pos = atomicAdd(&s_cnt, 1);
            if (pos < 128) sel[pos] = key;
        }
    }
    __syncthreads();

    for (int kk2 = 2; kk2 <= 128; kk2 <<= 1) {
        for (int jj = kk2 >> 1; jj > 0; jj >>= 1) {
            if (t < 128) {
                int ixj = t ^ jj;
                if (ixj > t) {
                    u64 a = sel[t], b = sel[ixj];
                    bool up = ((t & kk2) == 0);
                    if (up ? (a > b) : (a < b)) { sel[t] = b; sel[ixj] = a; }
                }
            }
            __syncthreads();
        }
    }

    // output buffer is float32 (indices exact below 2^24)
    if (t < TOPK) out[q * TOPK + t] = (float)(u32)(sel[t] & 0xFFFFFFFFu);
}

// =============================================================================
// launch — mapping verified by round-7 diagnostics (dict order):
//   d_in[0]=queries d_in[1]=centroids d_in[2]=codebooks
//   d_in[3]=db_codes d_in[4]=db_list d_in[5]=top_k(scalar)
// =============================================================================
extern "C" void kernel_launch(void* const* d_in, const int* in_sizes, int n_in,
                              void* d_out, int out_size)
{
    const float* queries   = (const float*)d_in[0];
    const float* centroids = (const float*)d_in[1];
    const float* codebooks = (const float*)d_in[2];
    const int*   db_codes  = (const int*)d_in[3];
    const int*   db_list   = (const int*)d_in[4];
    int N = in_sizes[4];
    if (N <= 0 || N > MAXN) N = MAXN;
    float* out = (float*)d_out;

    k_cnorm<<<128, 256>>>(centroids);
    k_fused<<<QN, 256>>>(queries, codebooks, db_codes, db_list, centroids, N, out);
}

// round 12
// speedup vs baseline: 2.9789x; 2.9789x over previous
#include <cuda_runtime.h>
#include <stdint.h>

#define QN     256
#define DIM    128
#define NLIST  1024
#define MSUB   8
#define KCODE  256
#define DSUB   16
#define NPROBE 32
#define TOPK   100
#define MAXN   250000
#define NBIN   4096
#define BUFSZ  4096

typedef unsigned long long u64;
typedef unsigned int       u32;

// ---------------- device scratch (static: allocation-free) ------------------
__device__ float g_cnf[NLIST];          // centroid norms (XLA-reduce order)
__device__ int   g_counts[NLIST];
__device__ int   g_starts[NLIST];
__device__ int   g_cursor[NLIST];
__device__ int   g_inv[MAXN];           // point id per inverted slot
__device__ int4  g_codes[2 * MAXN];     // codes gathered into inverted order

// monotonic float->uint transform (total order preserving)
__device__ __forceinline__ u32 f2s(float f) {
    u32 u = __float_as_uint(f);
    return u ^ ((u >> 31) ? 0xFFFFFFFFu : 0x80000000u);
}

// XLA-GPU style row-norm: lane sums 4 CONTIGUOUS rounded products
// sequentially, then shfl-down butterfly (16,8,4,2,1). Valid in lane 0.
__device__ __forceinline__ float warp_norm128(const float* __restrict__ row, int lane)
{
    float p0 = __fmul_rn(row[4 * lane + 0], row[4 * lane + 0]);
    float p1 = __fmul_rn(row[4 * lane + 1], row[4 * lane + 1]);
    float p2 = __fmul_rn(row[4 * lane + 2], row[4 * lane + 2]);
    float p3 = __fmul_rn(row[4 * lane + 3], row[4 * lane + 3]);
    float s  = __fadd_rn(__fadd_rn(__fadd_rn(p0, p1), p2), p3);
    #pragma unroll
    for (int off = 16; off > 0; off >>= 1)
        s = __fadd_rn(s, __shfl_down_sync(0xFFFFFFFFu, s, off));
    return s;
}

// ---------------- index build ------------------------------------------------
__global__ void __launch_bounds__(256) k_cnorm(const float* __restrict__ centroids)
{
    int wid  = blockIdx.x * 8 + (threadIdx.x >> 5);
    int lane = threadIdx.x & 31;
    if (wid < NLIST) {
        float s = warp_norm128(centroids + (size_t)wid * DIM, lane);
        if (lane == 0) g_cnf[wid] = s;
    }
    int gtid = blockIdx.x * 256 + threadIdx.x;
    if (gtid < NLIST) g_counts[gtid] = 0;
}

__global__ void __launch_bounds__(256) k_hist(const int* __restrict__ db_list, int N)
{
    __shared__ int sh[NLIST];
    int t = threadIdx.x;
    for (int i = t; i < NLIST; i += 256) sh[i] = 0;
    __syncthreads();
    for (int n = blockIdx.x * 256 + t; n < N; n += gridDim.x * 256)
        atomicAdd(&sh[db_list[n] & (NLIST - 1)], 1);
    __syncthreads();
    for (int i = t; i < NLIST; i += 256)
        if (sh[i]) atomicAdd(&g_counts[i], sh[i]);
}

__global__ void __launch_bounds__(1024) k_scan()
{
    __shared__ int s[NLIST];
    int t = threadIdx.x;
    int c = g_counts[t];
    s[t] = c;
    __syncthreads();
    for (int off = 1; off < NLIST; off <<= 1) {
        int v = (t >= off) ? s[t - off] : 0;
        __syncthreads();
        s[t] += v;
        __syncthreads();
    }
    g_starts[t] = s[t] - c;
    g_cursor[t] = s[t] - c;
}

__global__ void __launch_bounds__(256) k_scatter(const int* __restrict__ db_list,
                                                 const int* __restrict__ db_codes,
                                                 int N)
{
    for (int n = blockIdx.x * 256 + threadIdx.x; n < N; n += gridDim.x * 256) {
        int l   = db_list[n] & (NLIST - 1);
        int pos = atomicAdd(&g_cursor[l], 1);
        const int4* cp = (const int4*)(db_codes + (size_t)n * MSUB);
        g_inv[pos] = n;
        g_codes[2 * pos]     = __ldg(cp);
        g_codes[2 * pos + 1] = __ldg(cp + 1);
    }
}

// =============================================================================
// k_search: one CTA per query.
//   phase 1: coarse dists (bit-identical to round-11 numerics) -> top-32 lists
//   phase 2: ADC LUT (bit-identical)
//   phase 3: walk the 32 inverted lists (~7800 pts): histogram pass + collect
//   phase 4: exact radix select + compact + bitonic 128 -> top-100 (as float)
// =============================================================================
__global__ void __launch_bounds__(256) k_search(const float* __restrict__ queries,
                                                const float* __restrict__ codebooks,
                                                const float* __restrict__ centroids,
                                                float* __restrict__ out)
{
    __shared__ __align__(16) unsigned char SM[32768];   // phase-aliased
    u64* ckey   = (u64*)SM;            // phase 1: 1024 coarse keys
    u32* hist4k = (u32*)SM;            // phase 3a: 4096-bin histogram
    u64* buf    = (u64*)SM;            // phase 3b: collected keys

    __shared__ float lut[MSUB * KCODE];
    __shared__ float qsm[DIM];
    __shared__ u32   hist256[256];
    __shared__ u64   sel[128];
    __shared__ u64   wmin[8];
    __shared__ u64   s_g;
    __shared__ float s_qnf;
    __shared__ int   s_list[NPROBE], s_start[NPROBE], s_cn[NPROBE], s_pcum[NPROBE + 1];
    __shared__ int   s_cnt, s_k, s_bstar;
    __shared__ u32   s_pfx;

    int t = threadIdx.x;
    int q = blockIdx.x;

    if (t < DIM) qsm[t] = queries[q * DIM + t];
    if (t == 0) { s_cnt = 0; s_bstar = -1; }
    __syncthreads();

    // ---------- phase 1: coarse distances (reference-order f32) -------------
    if (t < 32) {
        float s = warp_norm128(qsm, t);
        if (t == 0) s_qnf = s;
    }
    __syncthreads();
    float qnf = s_qnf;

    #pragma unroll
    for (int s = 0; s < 4; ++s) {
        int l = t + s * 256;
        const float* cr = centroids + (size_t)l * DIM;
        float dq = 0.f;                        // sequential FMA, k ascending
        #pragma unroll 8
        for (int d = 0; d < DIM; ++d)
            dq = __fmaf_rn(qsm[d], __ldg(cr + d), dq);
        float dist = __fsub_rn(__fadd_rn(qnf, g_cnf[l]), __fmul_rn(2.f, dq));
        ckey[l] = (((u64)f2s(dist)) << 32) | (u32)l;
    }
    __syncthreads();

    // exact top-32 via 32 rounds of block argmin (keys unique)
    for (int r = 0; r < NPROBE; ++r) {
        u64 lm = ~0ULL;
        #pragma unroll
        for (int s = 0; s < 4; ++s) { u64 k = ckey[t + s * 256]; if (k < lm) lm = k; }
        #pragma unroll
        for (int off = 16; off > 0; off >>= 1) {
            u64 o = __shfl_down_sync(0xFFFFFFFFu, lm, off);
            if (o < lm) lm = o;
        }
        if ((t & 31) == 0) wmin[t >> 5] = lm;
        __syncthreads();
        if (t == 0) {
            u64 g = wmin[0];
            #pragma unroll
            for (int w = 1; w < 8; ++w) if (wmin[w] < g) g = wmin[w];
            s_g = g;
            s_list[r] = (int)(g & (NLIST - 1));
        }
        __syncthreads();
        u64 g = s_g;
        #pragma unroll
        for (int s = 0; s < 4; ++s)
            if (ckey[t + s * 256] == g) ckey[t + s * 256] = ~0ULL;
        __syncthreads();
    }

    // fetch list extents, cumulative offsets
    if (t < NPROBE) {
        int l = s_list[t];
        s_start[t] = g_starts[l];
        s_cn[t]    = g_counts[l];
    }
    __syncthreads();
    if (t == 0) {
        int acc = 0;
        for (int i = 0; i < NPROBE; ++i) { s_pcum[i] = acc; acc += s_cn[i]; }
        s_pcum[NPROBE] = acc;
    }

    // ---------- phase 2: ADC LUT (reference-order f32) ----------------------
    #pragma unroll
    for (int m = 0; m < MSUB; ++m) {
        const float* cb = codebooks + ((size_t)(m * KCODE + t)) * DSUB;
        const float* qm = qsm + m * DSUB;
        float cn = 0.f, qns = 0.f, dq = 0.f;
        #pragma unroll
        for (int d = 0; d < DSUB; ++d) {
            float c = __ldg(cb + d);
            cn  = __fadd_rn(cn,  __fmul_rn(c, c));
            qns = __fadd_rn(qns, __fmul_rn(qm[d], qm[d]));
            dq  = __fmaf_rn(qm[d], c, dq);
        }
        lut[m * KCODE + t] = __fsub_rn(__fadd_rn(qns, cn), __fmul_rn(2.f, dq));
    }
    __syncthreads();   // ckey dead; SM becomes hist4k

    // ---------- phase 3a: histogram of 12-bit distance prefixes --------------
    for (int i = t; i < NBIN; i += 256) hist4k[i] = 0;
    __syncthreads();

    int total = s_pcum[NPROBE];
    #pragma unroll 1
    for (int i = 0; i < NPROBE; ++i) {
        int base = s_start[i], cnt = s_cn[i];
        for (int j = t; j < cnt; j += 256) {
            int4 c0 = g_codes[2 * (base + j)];
            int4 c1 = g_codes[2 * (base + j) + 1];
            float dsum = lut[c0.x & 255];          // sequential f32, m = 0..7
            dsum = __fadd_rn(dsum, lut[KCODE     + (c0.y & 255)]);
            dsum = __fadd_rn(dsum, lut[2 * KCODE + (c0.z & 255)]);
            dsum = __fadd_rn(dsum, lut[3 * KCODE + (c0.w & 255)]);
            dsum = __fadd_rn(dsum, lut[4 * KCODE + (c1.x & 255)]);
            dsum = __fadd_rn(dsum, lut[5 * KCODE + (c1.y & 255)]);
            dsum = __fadd_rn(dsum, lut[6 * KCODE + (c1.z & 255)]);
            dsum = __fadd_rn(dsum, lut[7 * KCODE + (c1.w & 255)]);
            u32 bin = f2s(dsum) >> 20;
            unsigned am = __activemask();
            u32 mm = __match_any_sync(am, bin);
            int leader = __ffs(mm) - 1;
            if ((t & 31) == leader) atomicAdd(&hist4k[bin], (u32)__popc(mm));
        }
    }
    __syncthreads();

    {
        u32 gsum = 0;
        #pragma unroll
        for (int i = 0; i < 16; ++i) gsum += hist4k[t * 16 + i];
        hist256[t] = gsum;
        __syncthreads();
        for (int off = 1; off < 256; off <<= 1) {
            u32 v = (t >= off) ? hist256[t - off] : 0u;
            __syncthreads();
            hist256[t] += v;
            __syncthreads();
        }
        int ksel = (total < TOPK) ? total : TOPK;
        u32 cumEnd   = hist256[t];
        u32 cumStart = cumEnd - gsum;
        if (total > 0 && (int)cumStart < ksel && (int)cumEnd >= ksel) {
            int c = (int)cumStart;
            #pragma unroll
            for (int i = 0; i < 16; ++i) {
                c += (int)hist4k[t * 16 + i];
                if (c >= ksel) { s_bstar = t * 16 + i; break; }
            }
        }
    }
    __syncthreads();

    int bstar = s_bstar;
    if (total == 0 || bstar < 0) {
        if (t < TOPK) out[q * TOPK + t] = 0.f;   // unreachable for this data
        return;
    }
    __syncthreads();   // hist4k dead; SM becomes buf

    // ---------- phase 3b: collect keys with prefix <= bstar ------------------
    if (t == 0) s_cnt = 0;
    __syncthreads();
    #pragma unroll 1
    for (int i = 0; i < NPROBE; ++i) {
        int base = s_start[i], cnt = s_cn[i];
        for (int j = t; j < cnt; j += 256) {
            int4 c0 = g_codes[2 * (base + j)];
            int4 c1 = g_codes[2 * (base + j) + 1];
            float dsum = lut[c0.x & 255];
            dsum = __fadd_rn(dsum, lut[KCODE     + (c0.y & 255)]);
            dsum = __fadd_rn(dsum, lut[2 * KCODE + (c0.z & 255)]);
            dsum = __fadd_rn(dsum, lut[3 * KCODE + (c0.w & 255)]);
            dsum = __fadd_rn(dsum, lut[4 * KCODE + (c1.x & 255)]);
            dsum = __fadd_rn(dsum, lut[5 * KCODE + (c1.y & 255)]);
            dsum = __fadd_rn(dsum, lut[6 * KCODE + (c1.z & 255)]);
            dsum = __fadd_rn(dsum, lut[7 * KCODE + (c1.w & 255)]);
            u32 dk = f2s(dsum);
            if ((int)(dk >> 20) <= bstar) {
                int pos = atomicAdd(&s_cnt, 1);
                if (pos < BUFSZ)
                    buf[pos] = (((u64)dk) << 32) | (u32)g_inv[base + j];
            }
        }
    }
    __syncthreads();

    int C = s_cnt;
    if (C > BUFSZ) C = BUFSZ;
    int ksel = (total < TOPK) ? total : TOPK;
    if (ksel > C) ksel = C;

    // ---------- phase 4a: exact radix select of ksel-th smallest dist key ----
    if (t == 0) { s_pfx = 0u; s_k = ksel; }
    int iters = (C + 255) >> 8;
    for (int pass = 3; pass >= 0; --pass) {
        __syncthreads();
        u32 prefix = s_pfx;
        int kk     = s_k;
        int shift  = pass * 8;
        u32 pmask  = (pass == 3) ? 0u : (0xFFFFFFFFu << (shift + 8));
        hist256[t] = 0;
        __syncthreads();
        for (int it = 0; it < iters; ++it) {
            int j = (it << 8) + t;
            if (j < C) {
                u32 dk = (u32)(buf[j] >> 32);
                if ((dk & pmask) == prefix)
                    atomicAdd(&hist256[(dk >> shift) & 0xFF], 1u);
            }
        }
        __syncthreads();
        for (int off = 1; off < 256; off <<= 1) {
            u32 v = (t >= off) ? hist256[t - off] : 0u;
            __syncthreads();
            hist256[t] += v;
            __syncthreads();
        }
        u32 cum  = hist256[t];
        u32 prev = (t == 0) ? 0u : hist256[t - 1];
        if ((int)cum >= kk && (int)prev < kk) {
            s_pfx = prefix | ((u32)t << shift);
            s_k   = kk - (int)prev;
        }
    }
    __syncthreads();
    u32 kth = s_pfx;

    // ---------- phase 4b: compact (<= kth), bitonic sort 128, emit -----------
    if (t == 0) s_cnt = 0;
    if (t < 128) sel[t] = ~0ULL;
    __syncthreads();
    for (int j = t; j < C; j += 256) {
        u64 key = buf[j];
        if ((u32)(key >> 32) <= kth) {
            int pos = atomicAdd(&s_cnt, 1);
            if (pos < 128) sel[pos] = key;
        }
    }
    __syncthreads();

    for (int kk2 = 2; kk2 <= 128; kk2 <<= 1) {
        for (int jj = kk2 >> 1; jj > 0; jj >>= 1) {
            if (t < 128) {
                int ixj = t ^ jj;
                if (ixj > t) {
                    u64 a = sel[t], b = sel[ixj];
                    bool up = ((t & kk2) == 0);
                    if (up ? (a > b) : (a < b)) { sel[t] = b; sel[ixj] = a; }
                }
            }
            __syncthreads();
        }
    }

    // output buffer is float32 (indices exact below 2^24)
    if (t < TOPK) out[q * TOPK + t] = (float)(u32)(sel[t] & 0xFFFFFFFFu);
}

// =============================================================================
// launch — input mapping verified by round-7 diagnostics (dict order)
// =============================================================================
extern "C" void kernel_launch(void* const* d_in, const int* in_sizes, int n_in,
                              void* d_out, int out_size)
{
    const float* queries   = (const float*)d_in[0];
    const float* centroids = (const float*)d_in[1];
    const float* codebooks = (const float*)d_in[2];
    const int*   db_codes  = (const int*)d_in[3];
    const int*   db_list   = (const int*)d_in[4];
    int N = in_sizes[4];
    if (N <= 0 || N > MAXN) N = MAXN;
    float* out = (float*)d_out;

    k_cnorm<<<128, 256>>>(centroids);
    k_hist<<<128, 256>>>(db_list, N);
    k_scan<<<1, 1024>>>();
    k_scatter<<<128, 256>>>(db_list, db_codes, N);
    k_search<<<QN, 256>>>(queries, codebooks, centroids, out);
}